// round 3
// baseline (speedup 1.0000x reference)
#include <cuda_runtime.h>

// ---------------------------------------------------------------------------
// QSRGAN quantum-circuit super-resolution
//   out[g, y, x, k] = s_k^2 / max_{j<16} s_j^2, s = circuit(angles(y,x); W_g)
// Two pixels per thread packed into f32x2 (FFMA2); weight sincos precomputed.
// ---------------------------------------------------------------------------

typedef unsigned long long u64;

#define NGEN   4
#define QD     6
#define NQ     5
#define NW     (QD * NQ)          // 30 weights per generator
#define H2     512
#define W2     512
#define HW     (H2 * W2)          // 262144 output pixels
#define NTHREADS_TOTAL (HW / 2)   // 131072 threads, 2 pixels each

// packed (c,c),(s,s) per gate per generator
__device__ ulonglong2 g_wcs[NGEN * NW];

// ---------------- packed f32x2 helpers ----------------
static __device__ __forceinline__ u64 pk2(float lo, float hi) {
    u64 r; asm("mov.b64 %0, {%1, %2};" : "=l"(r) : "f"(lo), "f"(hi)); return r;
}
static __device__ __forceinline__ float2 up2(u64 v) {
    float2 r; asm("mov.b64 {%0, %1}, %2;" : "=f"(r.x), "=f"(r.y) : "l"(v)); return r;
}
static __device__ __forceinline__ u64 m2(u64 a, u64 b) {
    u64 d; asm("mul.rn.f32x2 %0, %1, %2;" : "=l"(d) : "l"(a), "l"(b)); return d;
}
static __device__ __forceinline__ u64 f2(u64 a, u64 b, u64 c) {
    u64 d; asm("fma.rn.f32x2 %0, %1, %2, %3;" : "=l"(d) : "l"(a), "l"(b), "l"(c)); return d;
}
static __device__ __forceinline__ float rcpa(float x) {
    float r; asm("rcp.approx.f32 %0, %1;" : "=f"(r) : "f"(x)); return r;
}

// CZ diagonal sign mask: sign[i] = parity over adjacent bit pairs (4,3)..(1,0)
constexpr unsigned czmask_calc() {
    unsigned m = 0;
    for (int i = 0; i < 32; i++) {
        int p = 0;
        for (int y = 0; y < 4; y++)
            p ^= ((i >> (4 - y)) & 1) & ((i >> (3 - y)) & 1);
        if (p) m |= 1u << i;
    }
    return m;
}
static constexpr unsigned CZM  = czmask_calc();
static constexpr u64      SGN2 = 0x8000000080000000ull;  // negate both packed lanes

// ---------------- prep: weight sincos table (precise sincosf, runs once/graph) ----
__global__ void qsr_prep(const float* __restrict__ qp) {
    int t = threadIdx.x;
    if (t < NGEN * NW) {
        float s, c;
        sincosf(0.5f * qp[t], &s, &c);   // qp flat index = g*30 + d*5 + q, matches gate order
        g_wcs[t] = make_ulonglong2(pk2(c, c), pk2(s, s));
    }
}

// ---------------- main kernel ----------------
__global__ __launch_bounds__(256) void qsr_main(const float* __restrict__ x,
                                                float* __restrict__ out) {
    __shared__ ulonglong2 swcs[NGEN * NW];
    for (int i = threadIdx.x; i < NGEN * NW; i += blockDim.x) swcs[i] = g_wcs[i];
    __syncthreads();

    int t = blockIdx.x * blockDim.x + threadIdx.x;   // 0..131071
    int Y = t >> 8;                                  // output row   0..511
    int j = t & 255;                                 // input col; outputs X=2j (A), 2j+1 (B)

    // --- bilinear (jax.image.resize 'bilinear', half-pixel centers, edge-normalized)
    // rows: even Y -> 0.25*x[iy-1] + 0.75*x[iy]; odd Y -> 0.75*x[iy] + 0.25*x[iy+1]
    int iy = Y >> 1;
    int y0, y1; float wy0, wy1;
    if (Y & 1) { y0 = iy;                 y1 = (iy + 1 < 256) ? iy + 1 : 255; wy0 = 0.75f; wy1 = 0.25f; }
    else       { y0 = (iy > 0) ? iy - 1 : 0; y1 = iy;                        wy0 = 0.25f; wy1 = 0.75f; }
    int xm = (j > 0) ? j - 1 : 0;        // left neighbor for even output col (A)
    int xp = (j + 1 < 256) ? j + 1 : 255;  // right neighbor for odd output col (B)

    const float* r0 = x + (size_t)(y0 * 256) * NQ;
    const float* r1 = x + (size_t)(y1 * 256) * NQ;

    // encoding cos/sin, packed (pixelA, pixelB) per qubit
    u64 EC[NQ], ES[NQ];
#pragma unroll
    for (int c = 0; c < NQ; c++) {
        float vm0 = __ldg(r0 + xm * NQ + c), vj0 = __ldg(r0 + j * NQ + c), vp0 = __ldg(r0 + xp * NQ + c);
        float vm1 = __ldg(r1 + xm * NQ + c), vj1 = __ldg(r1 + j * NQ + c), vp1 = __ldg(r1 + xp * NQ + c);
        float rowm = wy0 * vm0 + wy1 * vm1;
        float rowj = wy0 * vj0 + wy1 * vj1;
        float rowp = wy0 * vp0 + wy1 * vp1;
        float angA = 0.25f * rowm + 0.75f * rowj;   // X = 2j   (even)
        float angB = 0.75f * rowj + 0.25f * rowp;   // X = 2j+1 (odd)
        float sA, cA, sB, cB;
        __sincosf(0.5f * angA, &sA, &cA);
        __sincosf(0.5f * angB, &sB, &cB);
        EC[c] = pk2(cA, cB);
        ES[c] = pk2(sA, sB);
    }

    size_t obase = (size_t)(Y * W2 + 2 * j) * 16;   // pixel A output base (g=0)

#pragma unroll 1
    for (int g = 0; g < NGEN; g++) {
        // --- encoding state = tensor product: bit p of index <-> qubit (4-p)
        u64 v[32];
        v[0]  = EC[0];
        v[16] = ES[0];
#pragma unroll
        for (int q = 1; q < NQ; q++) {
            const int st = 1 << (4 - q);
#pragma unroll
            for (int i = 0; i < 32; i += 2 * st) {
                v[i + st] = m2(v[i], ES[q]);
                v[i]      = m2(v[i], EC[q]);
            }
        }

        // --- 6 layers of (5 shared-weight RY gates + CZ sign diagonal)
        const ulonglong2* wg = &swcs[g * NW];
#pragma unroll 1
        for (int d = 0; d < QD; d++) {
#pragma unroll
            for (int q = 0; q < NQ; q++) {
                ulonglong2 cs = wg[d * NQ + q];
                u64 C = cs.x, S = cs.y, NS = S ^ SGN2;
                const int st = 1 << (4 - q);
#pragma unroll
                for (int i = 0; i < 32; i++) {
                    if (!(i & st)) {
                        u64 a0 = v[i], a1 = v[i + st];
                        v[i]      = f2(NS, a1, m2(C, a0));  // c*a0 - s*a1
                        v[i + st] = f2(S,  a0, m2(C, a1));  // s*a0 + c*a1
                    }
                }
            }
#pragma unroll
            for (int i = 0; i < 32; i++)
                if ((CZM >> i) & 1) v[i] ^= SGN2;           // sign flip, alu pipe
        }

        // --- epilogue: out = s^2 / max(s[0:16]^2)  (the prob-sum cancels exactly)
        float2 s2[16];
#pragma unroll
        for (int i = 0; i < 16; i++) s2[i] = up2(m2(v[i], v[i]));
        float mA = s2[0].x, mB = s2[0].y;
#pragma unroll
        for (int i = 1; i < 16; i++) { mA = fmaxf(mA, s2[i].x); mB = fmaxf(mB, s2[i].y); }
        float rA = rcpa(mA), rB = rcpa(mB);

        float* og = out + (size_t)g * ((size_t)HW * 16) + obase;
#pragma unroll
        for (int c = 0; c < 4; c++) {
            float4 oa = make_float4(s2[4*c+0].x * rA, s2[4*c+1].x * rA,
                                    s2[4*c+2].x * rA, s2[4*c+3].x * rA);
            float4 ob = make_float4(s2[4*c+0].y * rB, s2[4*c+1].y * rB,
                                    s2[4*c+2].y * rB, s2[4*c+3].y * rB);
            *reinterpret_cast<float4*>(og + 4 * c)      = oa;   // pixel A
            *reinterpret_cast<float4*>(og + 16 + 4 * c) = ob;   // pixel B
        }
    }
}

extern "C" void kernel_launch(void* const* d_in, const int* in_sizes, int n_in,
                              void* d_out, int out_size) {
    const float* x  = (const float*)d_in[0];   // [256,256,5] f32
    const float* qp = (const float*)d_in[1];   // [4,30] f32
    float* out = (float*)d_out;                // [4,512,512,16] f32

    qsr_prep<<<1, 128>>>(qp);
    qsr_main<<<NTHREADS_TOTAL / 256, 256>>>(x, out);
}

// round 4
// speedup vs baseline: 1.4116x; 1.4116x over previous
#include <cuda_runtime.h>

// ---------------------------------------------------------------------------
// QSRGAN quantum super-resolution, matrix-folded form.
//   out[g,y,x,k] = s_k^2 / max_{j<16} s_j^2,   s = M_g · e(pixel)
// where M_g = rows 0..15 of the fixed 30-gate weight circuit (precomputed),
// and e = tensor product of (1, tan(theta_q/2))  (global cos scale cancels).
// Two pixels per thread packed into f32x2. M streamed from smem as (m,m) u64.
// ---------------------------------------------------------------------------

typedef unsigned long long u64;

#define NGEN   4
#define QD     6
#define NQ     5
#define NW     (QD * NQ)
#define KEEP   16
#define DIM    32
#define H2     512
#define W2     512
#define HW     (H2 * W2)
#define NTHREADS_TOTAL (HW / 2)

// M_g[k][i] duplicated into both f32x2 lanes, flat index (g*16 + k)*32 + i
__device__ u64 g_M[NGEN * KEEP * DIM];

// ---------------- packed f32x2 helpers ----------------
static __device__ __forceinline__ u64 pk2(float lo, float hi) {
    u64 r; asm("mov.b64 %0, {%1, %2};" : "=l"(r) : "f"(lo), "f"(hi)); return r;
}
static __device__ __forceinline__ float2 up2(u64 v) {
    float2 r; asm("mov.b64 {%0, %1}, %2;" : "=f"(r.x), "=f"(r.y) : "l"(v)); return r;
}
static __device__ __forceinline__ u64 m2(u64 a, u64 b) {
    u64 d; asm("mul.rn.f32x2 %0, %1, %2;" : "=l"(d) : "l"(a), "l"(b)); return d;
}
static __device__ __forceinline__ u64 f2(u64 a, u64 b, u64 c) {
    u64 d; asm("fma.rn.f32x2 %0, %1, %2, %3;" : "=l"(d) : "l"(a), "l"(b), "l"(c)); return d;
}
static __device__ __forceinline__ float rcpa(float x) {
    float r; asm("rcp.approx.f32 %0, %1;" : "=f"(r) : "f"(x)); return r;
}

// CZ diagonal sign mask (adjacent-qubit CZ ladder)
constexpr unsigned czmask_calc() {
    unsigned m = 0;
    for (int i = 0; i < 32; i++) {
        int p = 0;
        for (int y = 0; y < 4; y++)
            p ^= ((i >> (4 - y)) & 1) & ((i >> (3 - y)) & 1);
        if (p) m |= 1u << i;
    }
    return m;
}
static constexpr unsigned CZM = czmask_calc();

// ---------------- prep: build M_g by simulating the circuit on basis vectors ----
__global__ void qsr_prep(const float* __restrict__ qp) {
    int t = threadIdx.x;                 // 128 threads: (g, basis column j)
    if (t >= NGEN * DIM) return;
    int g = t >> 5, j = t & 31;

    float st[DIM];
#pragma unroll
    for (int i = 0; i < DIM; i++) st[i] = 0.0f;
    st[j] = 1.0f;

#pragma unroll 1
    for (int d = 0; d < QD; d++) {
#pragma unroll
        for (int q = 0; q < NQ; q++) {
            float s, c;
            sincosf(0.5f * qp[g * NW + d * NQ + q], &s, &c);
            const int str = 1 << (4 - q);
#pragma unroll
            for (int i = 0; i < DIM; i++) {
                if (!(i & str)) {
                    float a0 = st[i], a1 = st[i + str];
                    st[i]       = c * a0 - s * a1;
                    st[i + str] = s * a0 + c * a1;
                }
            }
        }
#pragma unroll
        for (int i = 0; i < DIM; i++)
            if ((CZM >> i) & 1) st[i] = -st[i];
    }
#pragma unroll
    for (int k = 0; k < KEEP; k++)
        g_M[(g * KEEP + k) * DIM + j] = pk2(st[k], st[k]);
}

// ---------------- main kernel ----------------
__global__ __launch_bounds__(256, 2) void qsr_main(const float* __restrict__ x,
                                                   float* __restrict__ out) {
    __shared__ alignas(16) u64 sM[NGEN * KEEP * DIM];   // 16 KB
    for (int i = threadIdx.x; i < NGEN * KEEP * DIM; i += 256) sM[i] = g_M[i];
    __syncthreads();

    int t = blockIdx.x * blockDim.x + threadIdx.x;   // 0..131071
    int Y = t >> 8;                                  // output row
    int j = t & 255;                                 // input col; outputs X=2j (A), 2j+1 (B)

    // --- bilinear (half-pixel centers, edge clamp) ---
    int iy = Y >> 1;
    int y0, y1; float wy0, wy1;
    if (Y & 1) { y0 = iy;                  y1 = (iy + 1 < 256) ? iy + 1 : 255; wy0 = 0.75f; wy1 = 0.25f; }
    else       { y0 = (iy > 0) ? iy - 1 : 0; y1 = iy;                          wy0 = 0.25f; wy1 = 0.75f; }
    int xm = (j > 0) ? j - 1 : 0;
    int xp = (j + 1 < 256) ? j + 1 : 255;

    const float* r0 = x + (size_t)(y0 * 256) * NQ;
    const float* r1 = x + (size_t)(y1 * 256) * NQ;

    // encoding tangents, packed (pixelA, pixelB)
    u64 ET[NQ];
#pragma unroll
    for (int c = 0; c < NQ; c++) {
        float vm0 = __ldg(r0 + xm * NQ + c), vj0 = __ldg(r0 + j * NQ + c), vp0 = __ldg(r0 + xp * NQ + c);
        float vm1 = __ldg(r1 + xm * NQ + c), vj1 = __ldg(r1 + j * NQ + c), vp1 = __ldg(r1 + xp * NQ + c);
        float rowm = wy0 * vm0 + wy1 * vm1;
        float rowj = wy0 * vj0 + wy1 * vj1;
        float rowp = wy0 * vp0 + wy1 * vp1;
        float angA = 0.25f * rowm + 0.75f * rowj;
        float angB = 0.75f * rowj + 0.25f * rowp;
        float sA, cA, sB, cB;
        __sincosf(0.5f * angA, &sA, &cA);
        __sincosf(0.5f * angB, &sB, &cB);
        ET[c] = pk2(sA * rcpa(cA), sB * rcpa(cB));   // tan(theta/2), both lanes
    }

    // --- e = tensor product of (1, t_q); e[0] = 1, 31 multiplies ---
    u64 e[DIM];
    e[0] = pk2(1.0f, 1.0f);
#pragma unroll
    for (int q = 0; q < NQ; q++) {
        const int st = 1 << (4 - q);
#pragma unroll
        for (int i = 0; i < DIM; i += 2 * st)
            e[i + st] = m2(e[i], ET[q]);
    }

    size_t obase = (size_t)(Y * W2 + 2 * j) * 16;

#pragma unroll 1
    for (int g = 0; g < NGEN; g++) {
        const u64* Mg = sM + g * KEEP * DIM;
        u64 s[KEEP];

        // 16x32 matvec, two interleaved rows for ILP; all LDS are uniform
        // broadcasts with immediate offsets (LDS.128 = two (m,m) pairs)
#pragma unroll
        for (int kk = 0; kk < KEEP / 2; kk++) {
            const ulonglong2* mk0 = reinterpret_cast<const ulonglong2*>(Mg + (2 * kk)     * DIM);
            const ulonglong2* mk1 = reinterpret_cast<const ulonglong2*>(Mg + (2 * kk + 1) * DIM);
            ulonglong2 a0 = mk0[0], b0 = mk1[0];
            u64 acc0 = f2(a0.y, e[1], a0.x);     // e[0] == 1
            u64 acc1 = f2(b0.y, e[1], b0.x);
#pragma unroll
            for (int ii = 1; ii < 16; ii++) {
                ulonglong2 ma = mk0[ii];
                ulonglong2 mb = mk1[ii];
                acc0 = f2(ma.x, e[2 * ii],     acc0);
                acc1 = f2(mb.x, e[2 * ii],     acc1);
                acc0 = f2(ma.y, e[2 * ii + 1], acc0);
                acc1 = f2(mb.y, e[2 * ii + 1], acc1);
            }
            s[2 * kk]     = acc0;
            s[2 * kk + 1] = acc1;
        }

        // --- epilogue: out = s^2 / max(s^2) ---
        float2 s2[KEEP];
#pragma unroll
        for (int i = 0; i < KEEP; i++) s2[i] = up2(m2(s[i], s[i]));
        float mA = s2[0].x, mB = s2[0].y;
#pragma unroll
        for (int i = 1; i < KEEP; i++) { mA = fmaxf(mA, s2[i].x); mB = fmaxf(mB, s2[i].y); }
        float rA = rcpa(mA), rB = rcpa(mB);

        float* og = out + (size_t)g * ((size_t)HW * 16) + obase;
#pragma unroll
        for (int c = 0; c < 4; c++) {
            float4 oa = make_float4(s2[4*c+0].x * rA, s2[4*c+1].x * rA,
                                    s2[4*c+2].x * rA, s2[4*c+3].x * rA);
            float4 ob = make_float4(s2[4*c+0].y * rB, s2[4*c+1].y * rB,
                                    s2[4*c+2].y * rB, s2[4*c+3].y * rB);
            *reinterpret_cast<float4*>(og + 4 * c)      = oa;   // pixel A
            *reinterpret_cast<float4*>(og + 16 + 4 * c) = ob;   // pixel B
        }
    }
}

extern "C" void kernel_launch(void* const* d_in, const int* in_sizes, int n_in,
                              void* d_out, int out_size) {
    const float* x  = (const float*)d_in[0];   // [256,256,5] f32
    const float* qp = (const float*)d_in[1];   // [4,30] f32
    float* out = (float*)d_out;                // [4,512,512,16] f32

    qsr_prep<<<1, 128>>>(qp);
    qsr_main<<<NTHREADS_TOTAL / 256, 256>>>(x, out);
}